// round 16
// baseline (speedup 1.0000x reference)
#include <cuda_runtime.h>
#include <cuda_fp16.h>
#include <cstdint>

// Problem dims
#define BB   8
#define SS   4096
#define DD   1024
#define HH   16
#define DHH  64
#define TT   (BB*SS)      // 32768 tokens

// ---------------------------------------------------------------------------
// Scratch (static __device__ — no allocations allowed)
// ---------------------------------------------------------------------------
__device__ __half g_Xh[(size_t)TT * DD];          // x fp16        64 MiB
__device__ __half g_Wh[4][(size_t)DD * DD];       // weights fp16   8 MiB
__device__ __half g_Qh[(size_t)TT * DD];
__device__ __half g_Kh[(size_t)TT * DD];
__device__ __half g_Vh[(size_t)TT * DD];
__device__ __half g_Ch[(size_t)TT * DD];          // ctx fp16      64 MiB

// ---------------------------------------------------------------------------
// Fused fp32 -> fp16 convert, 4 float4 per thread (MLP=4).
// ---------------------------------------------------------------------------
struct CvtArgs {
    const float* x; const float* w[4];
    __half* xh; __half* wh;
};

#define XBLKS 8192
#define WBLKS 256

__global__ void __launch_bounds__(256) cvt_kernel(CvtArgs ca) {
    const int bid = blockIdx.x;
    const float* src; __half* dst; size_t base;
    if (bid < XBLKS) {
        base = (size_t)bid * 1024;
        src = ca.x; dst = ca.xh;
    } else {
        const int m = (bid - XBLKS) >> 8;
        base = (size_t)((bid - XBLKS) & 255) * 1024;
        src = ca.w[m]; dst = ca.wh + (size_t)m * DD * DD;
    }
    float4 v[4];
#pragma unroll
    for (int j = 0; j < 4; j++)
        v[j] = ((const float4*)src)[base + threadIdx.x + 256 * j];
#pragma unroll
    for (int j = 0; j < 4; j++) {
        const size_t i = base + threadIdx.x + 256 * j;
        ((__half2*)dst)[i * 2]     = __floats2half2_rn(v[j].x, v[j].y);
        ((__half2*)dst)[i * 2 + 1] = __floats2half2_rn(v[j].z, v[j].w);
    }
}

// ---------------------------------------------------------------------------
// Shared GEMM helpers
// ---------------------------------------------------------------------------
__device__ __forceinline__ void mma_f32(float c[4], uint32_t a0, uint32_t a1,
                                        uint32_t a2, uint32_t a3,
                                        uint32_t b0, uint32_t b1) {
    asm volatile(
        "mma.sync.aligned.m16n8k16.row.col.f32.f16.f16.f32 "
        "{%0,%1,%2,%3}, {%4,%5,%6,%7}, {%8,%9}, {%0,%1,%2,%3};\n"
        : "+f"(c[0]), "+f"(c[1]), "+f"(c[2]), "+f"(c[3])
        : "r"(a0), "r"(a1), "r"(a2), "r"(a3), "r"(b0), "r"(b1));
}

// f16-accumulate variant: D,C are 2x b32 (half2 pairs).
__device__ __forceinline__ void mma_f16(uint32_t d[2], uint32_t a0, uint32_t a1,
                                        uint32_t a2, uint32_t a3,
                                        uint32_t b0, uint32_t b1,
                                        uint32_t c0, uint32_t c1) {
    asm volatile(
        "mma.sync.aligned.m16n8k16.row.col.f16.f16.f16.f16 "
        "{%0,%1}, {%2,%3,%4,%5}, {%6,%7}, {%8,%9};\n"
        : "=r"(d[0]), "=r"(d[1])
        : "r"(a0), "r"(a1), "r"(a2), "r"(a3), "r"(b0), "r"(b1),
          "r"(c0), "r"(c1));
}

__device__ __forceinline__ void ldsm4(uint32_t& r0, uint32_t& r1,
                                      uint32_t& r2, uint32_t& r3, uint32_t a) {
    asm volatile("ldmatrix.sync.aligned.m8n8.x4.shared.b16 {%0,%1,%2,%3}, [%4];"
                 : "=r"(r0), "=r"(r1), "=r"(r2), "=r"(r3) : "r"(a));
}

__device__ __forceinline__ void cp16(uint32_t s, const void* g) {
    asm volatile("cp.async.cg.shared.global [%0], [%1], 16;" :: "r"(s), "l"(g));
}

__device__ __forceinline__ void mbar_init(uint32_t a, uint32_t cnt) {
    asm volatile("mbarrier.init.shared.b64 [%0], %1;" :: "r"(a), "r"(cnt) : "memory");
}
__device__ __forceinline__ void mbar_arrive(uint32_t a) {
    asm volatile("mbarrier.arrive.shared.b64 _, [%0];" :: "r"(a) : "memory");
}
__device__ __forceinline__ void cpasync_mbar_arrive_noinc(uint32_t a) {
    asm volatile("cp.async.mbarrier.arrive.noinc.shared.b64 [%0];" :: "r"(a) : "memory");
}
__device__ __forceinline__ void mbar_wait(uint32_t mbar, int parity) {
    asm volatile(
        "{\n\t.reg .pred P1;\n\t"
        "WAIT_LOOP_%=:\n\t"
        "mbarrier.try_wait.parity.shared.b64 P1, [%0], %1, 0x989680;\n\t"
        "@P1 bra.uni WAIT_DONE_%=;\n\t"
        "bra.uni WAIT_LOOP_%=;\n\t"
        "WAIT_DONE_%=:\n\t}"
        :: "r"(mbar), "r"(parity) : "memory");
}

#define SST 72                        // smem row stride (halfs)
#define BK  64
#define NKT 16                        // K=1024 / BK
#define SMEM_BYTES (110592 + 64)

// ---------------------------------------------------------------------------
// QKV GEMM: fp16-ACCUMULATE experiment. CTA tile 128x64, 4 consumer warps
// (64x32 each) + 1 producer warp. 4-stage ring (192 rows/stage). Per kt:
// fp16 accumulators (one chunk of K=64), spilled to fp32 after each kt.
// fp16 output.
// ---------------------------------------------------------------------------
struct GemmArgs {
    const __half* A;
    const __half* Bm[3];
    const float*  bias[3];
    void*         C[3];
};

#define QBN 64
#define QROWS 192                     // 128 A rows | 64 B rows
#define QSTAGE_B (QROWS * SST * 2)    // 27648
#define QNS 4

__global__ void __launch_bounds__(160, 2) gemm_qkv(GemmArgs args) {
    extern __shared__ __half smem[];

    const int z = blockIdx.z;
    const __half* __restrict__ A   = args.A;
    const __half* __restrict__ Bw  = args.Bm[z];
    const float* __restrict__ bias = args.bias[z];

    const int bn  = blockIdx.x * QBN;
    const int bm  = blockIdx.y * 128;
    const int tid = threadIdx.x;
    const int warp = tid >> 5, lane = tid & 31;

    const uint32_t sbase = (uint32_t)__cvta_generic_to_shared(smem);
    const uint32_t mb    = sbase + QNS * QSTAGE_B;
    auto fullb  = [&](int s) -> uint32_t { return mb + 8 * s; };
    auto emptyb = [&](int s) -> uint32_t { return mb + 32 + 8 * s; };
    auto srow = [&](int s, int r, int c) -> uint32_t {
        return sbase + (uint32_t)(((s * QROWS + r) * SST + c) * 2);
    };

    if (tid == 0) {
#pragma unroll
        for (int s = 0; s < QNS; s++) {
            mbar_init(fullb(s), 32);
            mbar_init(emptyb(s), 4);
        }
    }
    __syncthreads();

    if (warp == 4) {
        // producer: 1536 chunks per stage, 48 per lane
        for (int kt = 0; kt < NKT; kt++) {
            const int s = kt % QNS;
            if (kt >= QNS) mbar_wait(emptyb(s), ((kt / QNS) - 1) & 1);
            const int kc = kt * BK;
#pragma unroll 8
            for (int j = 0; j < 48; j++) {
                const int c   = lane + 32 * j;
                const int row = c >> 3;
                const int c8  = (c & 7) * 8;
                const __half* g = (row < 128)
                    ? A  + (size_t)(bm + row) * DD + kc + c8
                    : Bw + (size_t)(bn + row - 128) * DD + kc + c8;
                cp16(srow(s, row, c8), g);
            }
            cpasync_mbar_arrive_noinc(fullb(s));
        }
        return;
    }

    // consumers: warp tile 64x32
    const int wm = (warp >> 1) * 64;   // 0/64
    const int wn = (warp & 1) * 32;    // 0/32

    const int alr = lane & 15, alc = (lane >> 4) * 8;
    const int blr = ((lane >> 4) & 1) * 8 + (lane & 7);
    const int blc = ((lane >> 3) & 1) * 8;

    float acc[4][4][4];
#pragma unroll
    for (int i = 0; i < 4; i++)
#pragma unroll
        for (int j = 0; j < 4; j++)
#pragma unroll
            for (int r = 0; r < 4; r++) acc[i][j][r] = 0.f;

    for (int kt = 0; kt < NKT; kt++) {
        const int s = kt % QNS;
        mbar_wait(fullb(s), (kt / QNS) & 1);

        uint32_t hacc[4][4][2];        // fp16 accumulators for this kt
#pragma unroll
        for (int kk = 0; kk < 4; kk++) {
            const int k0 = kk * 16;
            uint32_t a[4][4], b[4][2];
#pragma unroll
            for (int i = 0; i < 4; i++)
                ldsm4(a[i][0], a[i][1], a[i][2], a[i][3],
                      srow(s, wm + i * 16 + alr, k0 + alc));
#pragma unroll
            for (int jp = 0; jp < 2; jp++)
                ldsm4(b[2 * jp][0], b[2 * jp][1],
                      b[2 * jp + 1][0], b[2 * jp + 1][1],
                      srow(s, 128 + wn + jp * 16 + blr, k0 + blc));
#pragma unroll
            for (int i = 0; i < 4; i++)
#pragma unroll
                for (int j = 0; j < 4; j++) {
                    const uint32_t c0 = (kk == 0) ? 0u : hacc[i][j][0];
                    const uint32_t c1 = (kk == 0) ? 0u : hacc[i][j][1];
                    mma_f16(hacc[i][j], a[i][0], a[i][1], a[i][2], a[i][3],
                            b[j][0], b[j][1], c0, c1);
                }
        }
        if (lane == 0) mbar_arrive(emptyb(s));

        // spill fp16 chunk into fp32 accumulators (fma/alu pipes, overlaps)
#pragma unroll
        for (int i = 0; i < 4; i++)
#pragma unroll
            for (int j = 0; j < 4; j++) {
                const float2 lo = __half22float2(*(__half2*)&hacc[i][j][0]);
                const float2 hi = __half22float2(*(__half2*)&hacc[i][j][1]);
                acc[i][j][0] += lo.x; acc[i][j][1] += lo.y;
                acc[i][j][2] += hi.x; acc[i][j][3] += hi.y;
            }
    }

    // epilogue: bias + fp16 store
    const int qr = lane >> 2, qc = lane & 3;
#pragma unroll
    for (int i = 0; i < 4; i++) {
#pragma unroll
        for (int j = 0; j < 4; j++) {
            const int row = bm + wm + i * 16 + qr;
            const int col = bn + wn + j * 8 + qc * 2;
            const float b0 = bias[col], b1 = bias[col + 1];
            __half* C = (__half*)args.C[z];
            *(__half2*)&C[(size_t)row * DD + col] =
                __floats2half2_rn(acc[i][j][0] + b0, acc[i][j][1] + b1);
            *(__half2*)&C[(size_t)(row + 8) * DD + col] =
                __floats2half2_rn(acc[i][j][2] + b0, acc[i][j][3] + b1);
        }
    }
}

// ---------------------------------------------------------------------------
// O-projection GEMM: fp32 accumulate (R14-proven). CTA tile 128x128,
// 4 consumer warps (64x64) + 1 producer, 3-stage ring, fp32 out.
// ---------------------------------------------------------------------------
#define OBN 128
#define OROWS 256
#define OSTAGE_B (OROWS * SST * 2)    // 36864
#define ONS 3

__global__ void __launch_bounds__(160, 2) gemm_o(GemmArgs args) {
    extern __shared__ __half smem[];

    const int z = blockIdx.z;
    const __half* __restrict__ A   = args.A;
    const __half* __restrict__ Bw  = args.Bm[z];
    const float* __restrict__ bias = args.bias[z];

    const int bn  = blockIdx.x * OBN;
    const int bm  = blockIdx.y * 128;
    const int tid = threadIdx.x;
    const int warp = tid >> 5, lane = tid & 31;

    const uint32_t sbase = (uint32_t)__cvta_generic_to_shared(smem);
    const uint32_t mb    = sbase + ONS * OSTAGE_B;
    auto fullb  = [&](int s) -> uint32_t { return mb + 8 * s; };
    auto emptyb = [&](int s) -> uint32_t { return mb + 32 + 8 * s; };
    auto srow = [&](int s, int r, int c) -> uint32_t {
        return sbase + (uint32_t)(((s * OROWS + r) * SST + c) * 2);
    };

    if (tid == 0) {
#pragma unroll
        for (int s = 0; s < ONS; s++) {
            mbar_init(fullb(s), 32);
            mbar_init(emptyb(s), 4);
        }
    }
    __syncthreads();

    if (warp == 4) {
        for (int kt = 0; kt < NKT; kt++) {
            const int s = kt % ONS;
            if (kt >= ONS) mbar_wait(emptyb(s), ((kt / ONS) - 1) & 1);
            const int kc = kt * BK;
#pragma unroll 8
            for (int j = 0; j < 64; j++) {
                const int c   = lane + 32 * j;
                const int row = c >> 3;
                const int c8  = (c & 7) * 8;
                const __half* g = (row < 128)
                    ? A  + (size_t)(bm + row) * DD + kc + c8
                    : Bw + (size_t)(bn + row - 128) * DD + kc + c8;
                cp16(srow(s, row, c8), g);
            }
            cpasync_mbar_arrive_noinc(fullb(s));
        }
        return;
    }

    const int wm = (warp >> 1) * 64;
    const int wn = (warp & 1) * 64;

    const int alr = lane & 15, alc = (lane >> 4) * 8;
    const int blr = ((lane >> 4) & 1) * 8 + (lane & 7);
    const int blc = ((lane >> 3) & 1) * 8;

    float acc[4][8][4];
#pragma unroll
    for (int i = 0; i < 4; i++)
#pragma unroll
        for (int j = 0; j < 8; j++)
#pragma unroll
            for (int r = 0; r < 4; r++) acc[i][j][r] = 0.f;

    for (int kt = 0; kt < NKT; kt++) {
        const int s = kt % ONS;
        mbar_wait(fullb(s), (kt / ONS) & 1);
#pragma unroll
        for (int kk = 0; kk < 4; kk++) {
            const int k0 = kk * 16;
            uint32_t a[4][4], b[8][2];
#pragma unroll
            for (int i = 0; i < 4; i++)
                ldsm4(a[i][0], a[i][1], a[i][2], a[i][3],
                      srow(s, wm + i * 16 + alr, k0 + alc));
#pragma unroll
            for (int jp = 0; jp < 4; jp++)
                ldsm4(b[2 * jp][0], b[2 * jp][1],
                      b[2 * jp + 1][0], b[2 * jp + 1][1],
                      srow(s, 128 + wn + jp * 16 + blr, k0 + blc));
#pragma unroll
            for (int i = 0; i < 4; i++)
#pragma unroll
                for (int j = 0; j < 8; j++)
                    mma_f32(acc[i][j], a[i][0], a[i][1], a[i][2], a[i][3],
                            b[j][0], b[j][1]);
        }
        if (lane == 0) mbar_arrive(emptyb(s));
    }

    const int qr = lane >> 2, qc = lane & 3;
#pragma unroll
    for (int i = 0; i < 4; i++) {
#pragma unroll
        for (int j = 0; j < 8; j++) {
            const int row = bm + wm + i * 16 + qr;
            const int col = bn + wn + j * 8 + qc * 2;
            const float b0 = bias[col], b1 = bias[col + 1];
            float* C = (float*)args.C[z];
            *(float2*)&C[(size_t)row * DD + col] =
                make_float2(acc[i][j][0] + b0, acc[i][j][1] + b1);
            *(float2*)&C[(size_t)(row + 8) * DD + col] =
                make_float2(acc[i][j][2] + b0, acc[i][j][3] + b1);
        }
    }
}

// ---------------------------------------------------------------------------
// Per-token attention over the HEAD axis. One warp per token; fp16 in/out.
// ---------------------------------------------------------------------------
__global__ void __launch_bounds__(64) attn_kernel(
    const __half* __restrict__ Q, const __half* __restrict__ K,
    const __half* __restrict__ V, __half* __restrict__ Ch) {
    __shared__ float sQ[2][DD], sK[2][DD], sV[2][DD];
    __shared__ float sS[2][HH][HH];

    const int warp = threadIdx.x >> 5, lane = threadIdx.x & 31;
    const size_t t = (size_t)blockIdx.x * 2 + warp;

    const __half2* q2 = (const __half2*)(Q + t * DD);
    const __half2* k2 = (const __half2*)(K + t * DD);
    const __half2* v2 = (const __half2*)(V + t * DD);
#pragma unroll
    for (int i = lane; i < DD / 2; i += 32) {
        ((float2*)sQ[warp])[i] = __half22float2(q2[i]);
        ((float2*)sK[warp])[i] = __half22float2(k2[i]);
        ((float2*)sV[warp])[i] = __half22float2(v2[i]);
    }
    __syncwarp();

    for (int p = lane; p < HH * HH; p += 32) {
        const int h = p >> 4, g = p & 15;
        const float* q = &sQ[warp][h * DHH];
        const float* k = &sK[warp][g * DHH];
        float s = 0.f;
#pragma unroll
        for (int d = 0; d < DHH; d++) s += q[d] * k[d];
        sS[warp][h][g] = s * 0.125f;
    }
    __syncwarp();

    if (lane < HH) {
        float mx = -1e30f;
#pragma unroll
        for (int g = 0; g < HH; g++) mx = fmaxf(mx, sS[warp][lane][g]);
        float sum = 0.f;
#pragma unroll
        for (int g = 0; g < HH; g++) {
            float e = expf(sS[warp][lane][g] - mx);
            sS[warp][lane][g] = e;
            sum += e;
        }
        const float inv = 1.f / sum;
#pragma unroll
        for (int g = 0; g < HH; g++) sS[warp][lane][g] *= inv;
    }
    __syncwarp();

    __half* out = Ch + t * DD;
    for (int o2 = lane; o2 < DD / 2; o2 += 32) {
        const int o = o2 * 2;
        const int h = o >> 6, d = o & 63;
        float c0 = 0.f, c1 = 0.f;
#pragma unroll
        for (int g = 0; g < HH; g++) {
            c0 += sS[warp][h][g] * sV[warp][g * DHH + d];
            c1 += sS[warp][h][g] * sV[warp][g * DHH + d + 1];
        }
        ((__half2*)out)[o2] = __floats2half2_rn(c0, c1);
    }
}

// ---------------------------------------------------------------------------
// Launch
// ---------------------------------------------------------------------------
extern "C" void kernel_launch(void* const* d_in, const int* in_sizes, int n_in,
                              void* d_out, int out_size) {
    (void)in_sizes; (void)n_in; (void)out_size;
    const float* x  = (const float*)d_in[0];
    const float* wq = (const float*)d_in[1];
    const float* bq = (const float*)d_in[2];
    const float* wk = (const float*)d_in[3];
    const float* bk = (const float*)d_in[4];
    const float* wv = (const float*)d_in[5];
    const float* bv = (const float*)d_in[6];
    const float* wo = (const float*)d_in[7];
    const float* bo = (const float*)d_in[8];
    float* out = (float*)d_out;

    __half *Xh, *Wh, *Qh, *Kh, *Vh, *Ch;
    cudaGetSymbolAddress((void**)&Xh, g_Xh);
    cudaGetSymbolAddress((void**)&Wh, g_Wh);
    cudaGetSymbolAddress((void**)&Qh, g_Qh);
    cudaGetSymbolAddress((void**)&Kh, g_Kh);
    cudaGetSymbolAddress((void**)&Vh, g_Vh);
    cudaGetSymbolAddress((void**)&Ch, g_Ch);
    const size_t WS = (size_t)DD * DD;

    cudaFuncSetAttribute(gemm_qkv,
                         cudaFuncAttributeMaxDynamicSharedMemorySize, SMEM_BYTES);
    cudaFuncSetAttribute(gemm_o,
                         cudaFuncAttributeMaxDynamicSharedMemorySize, SMEM_BYTES);

    // 1) converts to fp16
    CvtArgs ca;
    ca.x = x; ca.w[0] = wq; ca.w[1] = wk; ca.w[2] = wv; ca.w[3] = wo;
    ca.xh = Xh; ca.wh = Wh;
    cvt_kernel<<<XBLKS + 4 * WBLKS, 256>>>(ca);

    // 2) fused QKV GEMMs (fp16-accumulate experiment)
    GemmArgs ga;
    ga.A = Xh;
    ga.Bm[0] = Wh + 0 * WS; ga.Bm[1] = Wh + 1 * WS; ga.Bm[2] = Wh + 2 * WS;
    ga.bias[0] = bq; ga.bias[1] = bk; ga.bias[2] = bv;
    ga.C[0] = Qh; ga.C[1] = Kh; ga.C[2] = Vh;
    gemm_qkv<<<dim3(DD / QBN, TT / 128, 3), 160, SMEM_BYTES>>>(ga);

    // 3) per-token head-axis attention (fp16 in/out)
    attn_kernel<<<TT / 2, 64>>>(Qh, Kh, Vh, Ch);

    // 4) output projection (fp32 accumulate)
    GemmArgs go;
    go.A = Ch;
    go.Bm[0] = Wh + 3 * WS; go.Bm[1] = go.Bm[0]; go.Bm[2] = go.Bm[0];
    go.bias[0] = bo; go.bias[1] = bo; go.bias[2] = bo;
    go.C[0] = out; go.C[1] = out; go.C[2] = out;
    gemm_o<<<dim3(DD / OBN, TT / 128, 1), 160, SMEM_BYTES>>>(go);
}

// round 17
// speedup vs baseline: 1.1995x; 1.1995x over previous
#include <cuda_runtime.h>
#include <cuda_fp16.h>
#include <cstdint>

// Problem dims
#define BB   8
#define SS   4096
#define DD   1024
#define HH   16
#define DHH  64
#define TT   (BB*SS)      // 32768 tokens

// ---------------------------------------------------------------------------
// Scratch (static __device__ — no allocations allowed)
// ---------------------------------------------------------------------------
__device__ __half g_Xh[(size_t)TT * DD];          // x fp16        64 MiB
__device__ __half g_Wh[4][(size_t)DD * DD];       // weights fp16   8 MiB
__device__ __half g_Qh[(size_t)TT * DD];
__device__ __half g_Kh[(size_t)TT * DD];
__device__ __half g_Vh[(size_t)TT * DD];
__device__ __half g_Ch[(size_t)TT * DD];          // ctx fp16      64 MiB

// ---------------------------------------------------------------------------
// Fused fp32 -> fp16 convert, 4 float4 per thread (MLP=4).
// ---------------------------------------------------------------------------
struct CvtArgs {
    const float* x; const float* w[4];
    __half* xh; __half* wh;
};

#define XBLKS 8192
#define WBLKS 256

__global__ void __launch_bounds__(256) cvt_kernel(CvtArgs ca) {
    const int bid = blockIdx.x;
    const float* src; __half* dst; size_t base;
    if (bid < XBLKS) {
        base = (size_t)bid * 1024;
        src = ca.x; dst = ca.xh;
    } else {
        const int m = (bid - XBLKS) >> 8;
        base = (size_t)((bid - XBLKS) & 255) * 1024;
        src = ca.w[m]; dst = ca.wh + (size_t)m * DD * DD;
    }
    float4 v[4];
#pragma unroll
    for (int j = 0; j < 4; j++)
        v[j] = ((const float4*)src)[base + threadIdx.x + 256 * j];
#pragma unroll
    for (int j = 0; j < 4; j++) {
        const size_t i = base + threadIdx.x + 256 * j;
        ((__half2*)dst)[i * 2]     = __floats2half2_rn(v[j].x, v[j].y);
        ((__half2*)dst)[i * 2 + 1] = __floats2half2_rn(v[j].z, v[j].w);
    }
}

// ---------------------------------------------------------------------------
// Warp-specialized fp16 NT GEMM (R14-proven): C = A*B^T + bias.
// CTA = 160 threads: warps 0-3 consumers (64x64), warp 4 producer.
// 3-stage mbarrier ring, BK=64, 2 CTAs/SM.
// ---------------------------------------------------------------------------
struct GemmArgs {
    const __half* A;
    const __half* Bm[3];
    const float*  bias[3];
    void*         C[3];
};

#define BM 128
#define BN 128
#define BK 64
#define SST 72
#define NS 3
#define NKT 16
#define STG_ROWS (BM + BN)
#define STAGE_B (STG_ROWS * SST * 2)  // 36864
#define SMEM_BYTES (NS * STAGE_B + 64)

__device__ __forceinline__ void mma16816(float c[4], uint32_t a0, uint32_t a1,
                                         uint32_t a2, uint32_t a3,
                                         uint32_t b0, uint32_t b1) {
    asm volatile(
        "mma.sync.aligned.m16n8k16.row.col.f32.f16.f16.f32 "
        "{%0,%1,%2,%3}, {%4,%5,%6,%7}, {%8,%9}, {%0,%1,%2,%3};\n"
        : "+f"(c[0]), "+f"(c[1]), "+f"(c[2]), "+f"(c[3])
        : "r"(a0), "r"(a1), "r"(a2), "r"(a3), "r"(b0), "r"(b1));
}

__device__ __forceinline__ void ldsm4(uint32_t& r0, uint32_t& r1,
                                      uint32_t& r2, uint32_t& r3, uint32_t a) {
    asm volatile("ldmatrix.sync.aligned.m8n8.x4.shared.b16 {%0,%1,%2,%3}, [%4];"
                 : "=r"(r0), "=r"(r1), "=r"(r2), "=r"(r3) : "r"(a));
}

__device__ __forceinline__ void cp16(uint32_t s, const void* g) {
    asm volatile("cp.async.cg.shared.global [%0], [%1], 16;" :: "r"(s), "l"(g));
}

__device__ __forceinline__ void mbar_init(uint32_t a, uint32_t cnt) {
    asm volatile("mbarrier.init.shared.b64 [%0], %1;" :: "r"(a), "r"(cnt) : "memory");
}
__device__ __forceinline__ void mbar_arrive(uint32_t a) {
    asm volatile("mbarrier.arrive.shared.b64 _, [%0];" :: "r"(a) : "memory");
}
__device__ __forceinline__ void cpasync_mbar_arrive_noinc(uint32_t a) {
    asm volatile("cp.async.mbarrier.arrive.noinc.shared.b64 [%0];" :: "r"(a) : "memory");
}
__device__ __forceinline__ void mbar_wait(uint32_t mbar, int parity) {
    asm volatile(
        "{\n\t.reg .pred P1;\n\t"
        "WAIT_LOOP_%=:\n\t"
        "mbarrier.try_wait.parity.shared.b64 P1, [%0], %1, 0x989680;\n\t"
        "@P1 bra.uni WAIT_DONE_%=;\n\t"
        "bra.uni WAIT_LOOP_%=;\n\t"
        "WAIT_DONE_%=:\n\t}"
        :: "r"(mbar), "r"(parity) : "memory");
}

template <bool HALF_OUT>
__global__ void __launch_bounds__(160, 2) gemm_kernel(GemmArgs args) {
    extern __shared__ __half smem[];

    const int z = blockIdx.z;
    const __half* __restrict__ A   = args.A;
    const __half* __restrict__ Bw  = args.Bm[z];
    const float* __restrict__ bias = args.bias[z];

    const int bn  = blockIdx.x * BN;
    const int bm  = blockIdx.y * BM;
    const int tid = threadIdx.x;
    const int warp = tid >> 5, lane = tid & 31;

    const uint32_t sbase = (uint32_t)__cvta_generic_to_shared(smem);
    const uint32_t mb    = sbase + NS * STAGE_B;
    auto fullb  = [&](int s) -> uint32_t { return mb + 8 * s; };
    auto emptyb = [&](int s) -> uint32_t { return mb + 24 + 8 * s; };
    auto srow = [&](int s, int r, int c) -> uint32_t {
        return sbase + (uint32_t)(((s * STG_ROWS + r) * SST + c) * 2);
    };

    if (tid == 0) {
#pragma unroll
        for (int s = 0; s < NS; s++) {
            mbar_init(fullb(s), 32);
            mbar_init(emptyb(s), 4);
        }
    }
    __syncthreads();

    if (warp == 4) {
        for (int kt = 0; kt < NKT; kt++) {
            const int s = kt % NS;
            if (kt >= NS) mbar_wait(emptyb(s), ((kt / NS) - 1) & 1);
            const int kc = kt * BK;
#pragma unroll 8
            for (int j = 0; j < 64; j++) {
                const int c   = lane + 32 * j;
                const int row = c >> 3;
                const int c8  = (c & 7) * 8;
                const __half* g = (row < BM)
                    ? A  + (size_t)(bm + row) * DD + kc + c8
                    : Bw + (size_t)(bn + row - BM) * DD + kc + c8;
                cp16(srow(s, row, c8), g);
            }
            cpasync_mbar_arrive_noinc(fullb(s));
        }
        return;
    }

    const int wm = (warp >> 1) * 64;
    const int wn = (warp & 1) * 64;

    const int alr = lane & 15, alc = (lane >> 4) * 8;
    const int blr = ((lane >> 4) & 1) * 8 + (lane & 7);
    const int blc = ((lane >> 3) & 1) * 8;

    float acc[4][8][4];
#pragma unroll
    for (int i = 0; i < 4; i++)
#pragma unroll
        for (int j = 0; j < 8; j++)
#pragma unroll
            for (int r = 0; r < 4; r++) acc[i][j][r] = 0.f;

    for (int kt = 0; kt < NKT; kt++) {
        const int s = kt % NS;
        mbar_wait(fullb(s), (kt / NS) & 1);
#pragma unroll
        for (int kk = 0; kk < 4; kk++) {
            const int k0 = kk * 16;
            uint32_t a[4][4], b[8][2];
#pragma unroll
            for (int i = 0; i < 4; i++)
                ldsm4(a[i][0], a[i][1], a[i][2], a[i][3],
                      srow(s, wm + i * 16 + alr, k0 + alc));
#pragma unroll
            for (int jp = 0; jp < 4; jp++)
                ldsm4(b[2 * jp][0], b[2 * jp][1],
                      b[2 * jp + 1][0], b[2 * jp + 1][1],
                      srow(s, BM + wn + jp * 16 + blr, k0 + blc));
#pragma unroll
            for (int i = 0; i < 4; i++)
#pragma unroll
                for (int j = 0; j < 8; j++)
                    mma16816(acc[i][j], a[i][0], a[i][1], a[i][2], a[i][3],
                             b[j][0], b[j][1]);
        }
        if (lane == 0) mbar_arrive(emptyb(s));
    }

    const int qr = lane >> 2, qc = lane & 3;
#pragma unroll
    for (int i = 0; i < 4; i++) {
#pragma unroll
        for (int j = 0; j < 8; j++) {
            const int row = bm + wm + i * 16 + qr;
            const int col = bn + wn + j * 8 + qc * 2;
            const float b0 = bias[col], b1 = bias[col + 1];
            const float v00 = acc[i][j][0] + b0, v01 = acc[i][j][1] + b1;
            const float v10 = acc[i][j][2] + b0, v11 = acc[i][j][3] + b1;
            if (HALF_OUT) {
                __half* C = (__half*)args.C[z];
                *(__half2*)&C[(size_t)row * DD + col]       = __floats2half2_rn(v00, v01);
                *(__half2*)&C[(size_t)(row + 8) * DD + col] = __floats2half2_rn(v10, v11);
            } else {
                float* C = (float*)args.C[z];
                *(float2*)&C[(size_t)row * DD + col]       = make_float2(v00, v01);
                *(float2*)&C[(size_t)(row + 8) * DD + col] = make_float2(v10, v11);
            }
        }
    }
}

// ---------------------------------------------------------------------------
// Per-token attention over the HEAD axis — LDS-optimized.
// One warp per token (2 tokens / 64-thread block), fp16 in/out, fp32 math.
// Scores: lane owns head h = lane&15 (q-row cached in registers; k broadcast).
// Ctx:    lane owns (h = lane>>1, 32-wide d-slice); p-row cached; v broadcast.
// Arithmetic order identical to previous rounds (d- and g-sequential fp32).
// ---------------------------------------------------------------------------
__global__ void __launch_bounds__(64) attn_kernel(
    const __half* __restrict__ Q, const __half* __restrict__ K,
    const __half* __restrict__ V, __half* __restrict__ Ch) {
    __shared__ float sQ[2][DD], sK[2][DD], sV[2][DD];
    __shared__ float sS[2][HH][HH];

    const int warp = threadIdx.x >> 5, lane = threadIdx.x & 31;
    const size_t t = (size_t)blockIdx.x * 2 + warp;

    const __half2* q2 = (const __half2*)(Q + t * DD);
    const __half2* k2 = (const __half2*)(K + t * DD);
    const __half2* v2 = (const __half2*)(V + t * DD);
#pragma unroll
    for (int i = lane; i < DD / 2; i += 32) {
        ((float2*)sQ[warp])[i] = __half22float2(q2[i]);
        ((float2*)sK[warp])[i] = __half22float2(k2[i]);
        ((float2*)sV[warp])[i] = __half22float2(v2[i]);
    }
    __syncwarp();

    // scores: h fixed per lane (= lane&15); q cached in 16 float4 regs
    {
        const int h = lane & 15;
        float4 qv[16];
        const float4* q4 = (const float4*)&sQ[warp][h * DHH];
#pragma unroll
        for (int i = 0; i < 16; i++) qv[i] = q4[i];
#pragma unroll
        for (int j = 0; j < 8; j++) {
            const int g = (lane >> 4) + 2 * j;
            const float4* k4 = (const float4*)&sK[warp][g * DHH];
            float s = 0.f;
#pragma unroll
            for (int i = 0; i < 16; i++) {
                const float4 kv = k4[i];
                s += qv[i].x * kv.x; s += qv[i].y * kv.y;
                s += qv[i].z * kv.z; s += qv[i].w * kv.w;
            }
            sS[warp][h][g] = s * 0.125f;   // 1/sqrt(64)
        }
    }
    __syncwarp();

    // softmax over g (one lane per head row)
    if (lane < HH) {
        float mx = -1e30f;
#pragma unroll
        for (int g = 0; g < HH; g++) mx = fmaxf(mx, sS[warp][lane][g]);
        float sum = 0.f;
#pragma unroll
        for (int g = 0; g < HH; g++) {
            float e = expf(sS[warp][lane][g] - mx);
            sS[warp][lane][g] = e;
            sum += e;
        }
        const float inv = 1.f / sum;
#pragma unroll
        for (int g = 0; g < HH; g++) sS[warp][lane][g] *= inv;
    }
    __syncwarp();

    // ctx: lane owns head h = lane>>1 and d-slice [(lane&1)*32, +32)
    {
        const int h  = lane >> 1;
        const int d0 = (lane & 1) * 32;
        float p[16];
#pragma unroll
        for (int g = 0; g < 16; g++) p[g] = sS[warp][h][g];

        float c[32];
#pragma unroll
        for (int r = 0; r < 32; r++) c[r] = 0.f;
#pragma unroll
        for (int g = 0; g < 16; g++) {
            const float4* v4 = (const float4*)&sV[warp][g * DHH + d0];
            const float pg = p[g];
#pragma unroll
            for (int q = 0; q < 8; q++) {
                const float4 vv = v4[q];
                c[q * 4 + 0] += pg * vv.x; c[q * 4 + 1] += pg * vv.y;
                c[q * 4 + 2] += pg * vv.z; c[q * 4 + 3] += pg * vv.w;
            }
        }
        __half2* out2 = (__half2*)(Ch + t * DD + h * DHH + d0);
#pragma unroll
        for (int q = 0; q < 16; q++)
            out2[q] = __floats2half2_rn(c[2 * q], c[2 * q + 1]);
    }
}

// ---------------------------------------------------------------------------
// Launch
// ---------------------------------------------------------------------------
extern "C" void kernel_launch(void* const* d_in, const int* in_sizes, int n_in,
                              void* d_out, int out_size) {
    (void)in_sizes; (void)n_in; (void)out_size;
    const float* x  = (const float*)d_in[0];
    const float* wq = (const float*)d_in[1];
    const float* bq = (const float*)d_in[2];
    const float* wk = (const float*)d_in[3];
    const float* bk = (const float*)d_in[4];
    const float* wv = (const float*)d_in[5];
    const float* bv = (const float*)d_in[6];
    const float* wo = (const float*)d_in[7];
    const float* bo = (const float*)d_in[8];
    float* out = (float*)d_out;

    __half *Xh, *Wh, *Qh, *Kh, *Vh, *Ch;
    cudaGetSymbolAddress((void**)&Xh, g_Xh);
    cudaGetSymbolAddress((void**)&Wh, g_Wh);
    cudaGetSymbolAddress((void**)&Qh, g_Qh);
    cudaGetSymbolAddress((void**)&Kh, g_Kh);
    cudaGetSymbolAddress((void**)&Vh, g_Vh);
    cudaGetSymbolAddress((void**)&Ch, g_Ch);
    const size_t WS = (size_t)DD * DD;

    cudaFuncSetAttribute(gemm_kernel<true>,
                         cudaFuncAttributeMaxDynamicSharedMemorySize, SMEM_BYTES);
    cudaFuncSetAttribute(gemm_kernel<false>,
                         cudaFuncAttributeMaxDynamicSharedMemorySize, SMEM_BYTES);

    // 1) fused converts to fp16
    CvtArgs ca;
    ca.x = x; ca.w[0] = wq; ca.w[1] = wk; ca.w[2] = wv; ca.w[3] = wo;
    ca.xh = Xh; ca.wh = Wh;
    cvt_kernel<<<XBLKS + 4 * WBLKS, 256>>>(ca);

    // 2) fused QKV GEMMs -> fp16
    GemmArgs ga;
    ga.A = Xh;
    ga.Bm[0] = Wh + 0 * WS; ga.Bm[1] = Wh + 1 * WS; ga.Bm[2] = Wh + 2 * WS;
    ga.bias[0] = bq; ga.bias[1] = bk; ga.bias[2] = bv;
    ga.C[0] = Qh; ga.C[1] = Kh; ga.C[2] = Vh;
    gemm_kernel<true><<<dim3(DD / BN, TT / BM, 3), 160, SMEM_BYTES>>>(ga);

    // 3) per-token head-axis attention (fp16 in/out)
    attn_kernel<<<TT / 2, 64>>>(Qh, Kh, Vh, Ch);

    // 4) output projection -> fp32 d_out
    GemmArgs go;
    go.A = Ch;
    go.Bm[0] = Wh + 3 * WS; go.Bm[1] = go.Bm[0]; go.Bm[2] = go.Bm[0];
    go.bias[0] = bo; go.bias[1] = bo; go.bias[2] = bo;
    go.C[0] = out; go.C[1] = out; go.C[2] = out;
    gemm_kernel<false><<<dim3(DD / BN, TT / BM, 1), 160, SMEM_BYTES>>>(go);
}